// round 1
// baseline (speedup 1.0000x reference)
#include <cuda_runtime.h>

// SecondOrderFeatureInteraction: out[b, pair(i,j)] = dot(x[b,i,:], x[b,j,:]) for i<j
// B=8192, N=32, D=256 fp32. Output [B, 496], row-major upper-tri ordering.

static constexpr int NF      = 32;    // feature fields
static constexpr int DD      = 256;   // embedding dim
static constexpr int NPAIRS  = 496;   // 32*31/2
static constexpr int NTILES  = 36;    // 8x8 grid of 4x4 tiles, upper incl. diagonal
static constexpr int KSLICES = 8;     // 32 k-values per slice
static constexpr int BLOCK   = NTILES * KSLICES;  // 288 threads (9 warps)
static constexpr int PSTRIDE = 17;    // padded partial stash stride (floats)

__global__ __launch_bounds__(BLOCK)
void soi_kernel(const float* __restrict__ x, float* __restrict__ out, int nbatch) {
    // Shared: phase 1 = x tile transposed to k-major: sm[k*32 + row], 8192 floats (32KB)
    //         phase 2 (reused) = partial accumulators: sm[tid*17 + e], 4896 floats
    __shared__ float sm[DD * NF];

    const int b    = blockIdx.x;
    const int tid  = threadIdx.x;
    const int lane = tid & 31;
    const int w    = tid >> 5;   // warp id 0..8
    const float* xb = x + (long long)b * (NF * DD);

    // ---- Load + transpose: global [row][k] -> shared [k][row] ----
    // lane == row, whole warp shares one k4 -> STS.32 banks == lane (conflict-free).
    for (int k4 = w; k4 < DD / 4; k4 += BLOCK / 32) {
        float4 v = *(const float4*)(xb + lane * DD + 4 * k4);
        const int kb = 4 * k4;
        sm[(kb + 0) * NF + lane] = v.x;
        sm[(kb + 1) * NF + lane] = v.y;
        sm[(kb + 2) * NF + lane] = v.z;
        sm[(kb + 3) * NF + lane] = v.w;
    }
    __syncthreads();

    // ---- Compute: thread = (tile t, k-slice s). 4x4 register tile over 32 k. ----
    const int t = tid % NTILES;
    const int s = tid / NTILES;
    int ti = 0, rem = t;
    while (rem >= 8 - ti) { rem -= 8 - ti; ti++; }
    const int tj = ti + rem;   // tj >= ti

    float acc[16];
    #pragma unroll
    for (int e = 0; e < 16; e++) acc[e] = 0.f;

    const int k0 = 32 * s;
    #pragma unroll 8
    for (int kk = 0; kk < 32; kk++) {
        const float* p = sm + (k0 + kk) * NF;
        const float4 av = *(const float4*)(p + 4 * ti);  // rows 4ti..4ti+3 at k (broadcast-shared)
        const float4 bv = *(const float4*)(p + 4 * tj);  // rows 4tj..4tj+3 at k
        acc[ 0] += av.x * bv.x;  acc[ 1] += av.x * bv.y;  acc[ 2] += av.x * bv.z;  acc[ 3] += av.x * bv.w;
        acc[ 4] += av.y * bv.x;  acc[ 5] += av.y * bv.y;  acc[ 6] += av.y * bv.z;  acc[ 7] += av.y * bv.w;
        acc[ 8] += av.z * bv.x;  acc[ 9] += av.z * bv.y;  acc[10] += av.z * bv.z;  acc[11] += av.z * bv.w;
        acc[12] += av.w * bv.x;  acc[13] += av.w * bv.y;  acc[14] += av.w * bv.z;  acc[15] += av.w * bv.w;
    }
    __syncthreads();   // all reads of x tile done; reuse sm for partials

    // ---- Stash partials: sm[tid*17 + e]  (banks = (17*tid+e)%32, conflict-free) ----
    #pragma unroll
    for (int e = 0; e < 16; e++) sm[tid * PSTRIDE + e] = acc[e];
    __syncthreads();

    // ---- Reduce 8 k-slices per tile element, map to output pair index ----
    for (int slot = tid; slot < NTILES * 16; slot += BLOCK) {
        const int tt = slot >> 4;
        const int e  = slot & 15;
        int a2 = 0, rr = tt;
        while (rr >= 8 - a2) { rr -= 8 - a2; a2++; }
        const int b2 = a2 + rr;
        const int i = 4 * a2 + (e >> 2);
        const int j = 4 * b2 + (e & 3);
        if (j <= i) continue;  // diagonal-tile lower/diag entries don't exist
        float sum = 0.f;
        #pragma unroll
        for (int ss = 0; ss < KSLICES; ss++)
            sum += sm[(ss * NTILES + tt) * PSTRIDE + e];
        const int idx = i * 31 - (i * (i - 1)) / 2 + (j - i - 1);
        out[(long long)b * NPAIRS + idx] = sum;
    }
}

extern "C" void kernel_launch(void* const* d_in, const int* in_sizes, int n_in,
                              void* d_out, int out_size) {
    const float* x = (const float*)d_in[0];
    float* out = (float*)d_out;
    const int nbatch = in_sizes[0] / (NF * DD);   // 8192
    soi_kernel<<<nbatch, BLOCK>>>(x, out, nbatch);
}

// round 3
// speedup vs baseline: 1.8443x; 1.8443x over previous
#include <cuda_runtime.h>
#include <cstdint>

// ─────────────────────────────────────────────────────────────────────────────
// SecondOrderFeatureInteraction via mma.sync.m16n8k8.tf32 batched Gram.
//   out[b, pair(i,j)] = dot(x[b,i,:], x[b,j,:]), i<j.  B=8192, N=32, D=256.
// One warp owns one batch: 32x32 gram in 24 accumulator regs, K=256 streamed
// through a 3-stage cp.async pipeline. B-fragments == A-fragments (Gram), so
// only 8 LDS.32 + 6 MMA per k-step per warp.
// ─────────────────────────────────────────────────────────────────────────────

static constexpr int NF = 32, DD = 256, NPAIRS = 496;
static constexpr int BLOCK = 256;                 // 8 warps
static constexpr int BPC = 8;                     // batches per CTA (1/warp)
static constexpr int KC = 32;                     // k-extent per stage
static constexpr int STAGE_BYTES = BPC * NF * KC * 4;   // 32 KB
static constexpr int NSTAGES = 3;
static constexpr int NKST = DD / KC;              // 8 k-stages

#define DI __device__ __forceinline__

DI uint32_t smem_u32(const void* p) {
    uint32_t a;
    asm("{ .reg .u64 t; cvta.to.shared.u64 t, %1; cvt.u32.u64 %0, t; }"
        : "=r"(a) : "l"(p));
    return a;
}

DI void cp_async16(uint32_t dst, const void* src) {
    asm volatile("cp.async.cg.shared.global [%0], [%1], 16;"
                 :: "r"(dst), "l"(src) : "memory");
}

DI float lds_f32(uint32_t a) {
    float v;
    asm volatile("ld.shared.f32 %0, [%1];" : "=f"(v) : "r"(a));
    return v;
}

DI uint32_t to_tf32(float f) {
    uint32_t r;
    asm("cvt.rna.tf32.f32 %0, %1;" : "=r"(r) : "f"(f));
    return r;
}

DI void mma_tf32(float* d, const uint32_t* a, uint32_t b0, uint32_t b1) {
    asm volatile(
        "mma.sync.aligned.m16n8k8.row.col.f32.tf32.tf32.f32 "
        "{%0,%1,%2,%3}, {%4,%5,%6,%7}, {%8,%9}, {%0,%1,%2,%3};"
        : "+f"(d[0]), "+f"(d[1]), "+f"(d[2]), "+f"(d[3])
        : "r"(a[0]), "r"(a[1]), "r"(a[2]), "r"(a[3]), "r"(b0), "r"(b1));
}

extern __shared__ char dynsmem[];

__global__ void __launch_bounds__(BLOCK, 2)
soi_mma_kernel(const float* __restrict__ x, float* __restrict__ out) {
    const uint32_t sb = smem_u32(dynsmem);
    const int tid = threadIdx.x, lane = tid & 31, wid = tid >> 5;
    const long long batch0 = (long long)blockIdx.x * BPC;
    const float* xg = x + batch0 * (NF * DD);

    // ── stage loader: 256 rows x 32 floats; smem row = 128B, 16B-chunk XOR swizzle
    auto load_stage = [&](int ks) {
        const uint32_t buf = sb + (ks % NSTAGES) * STAGE_BYTES;
        const float* src0 = xg + (long long)tid * DD + ks * KC;
        const uint32_t drow = buf + tid * 128;
        const int r7 = tid & 7;
        #pragma unroll
        for (int i = 0; i < 8; i++)
            cp_async16(drow + ((i ^ r7) << 4), src0 + i * 4);
        asm volatile("cp.async.commit_group;" ::: "memory");
    };

    // ── per-thread fragment addressing ──
    const int r7 = lane >> 2;                     // row-in-8 and swizzle key
    // element (row, k): buf + row*128 + ((k>>2 ^ row&7)<<4) + (k&3)*4
    const uint32_t rowA = (uint32_t)(wid * NF + r7) * 128 + (lane & 3) * 4;

    float acc[6][4];
    #pragma unroll
    for (int t = 0; t < 6; t++)
        #pragma unroll
        for (int e = 0; e < 4; e++) acc[t][e] = 0.f;

    load_stage(0);
    load_stage(1);

    for (int ks = 0; ks < NKST; ks++) {
        if (ks < NKST - 1)
            asm volatile("cp.async.wait_group 1;" ::: "memory");
        else
            asm volatile("cp.async.wait_group 0;" ::: "memory");
        __syncthreads();                          // all warps done with stage ks-1
        if (ks + 2 < NKST) load_stage(ks + 2);    // refill the retired buffer

        const uint32_t buf = sb + (ks % NSTAGES) * STAGE_BYTES;
        #pragma unroll
        for (int kq = 0; kq < 4; kq++) {
            const uint32_t o0 = (uint32_t)(((2 * kq + 0) ^ r7) << 4);
            const uint32_t o1 = (uint32_t)(((2 * kq + 1) ^ r7) << 4);
            const uint32_t base = buf + rowA;
            uint32_t a[8];
            a[0] = to_tf32(lds_f32(base + o0));          // m0 rows 0-7,  k lo
            a[1] = to_tf32(lds_f32(base + 1024 + o0));   // m0 rows 8-15, k lo
            a[2] = to_tf32(lds_f32(base + o1));          // m0 rows 0-7,  k hi
            a[3] = to_tf32(lds_f32(base + 1024 + o1));   // m0 rows 8-15, k hi
            a[4] = to_tf32(lds_f32(base + 2048 + o0));   // m1 rows 16-23, k lo
            a[5] = to_tf32(lds_f32(base + 3072 + o0));   // m1 rows 24-31, k lo
            a[6] = to_tf32(lds_f32(base + 2048 + o1));   // m1 rows 16-23, k hi
            a[7] = to_tf32(lds_f32(base + 3072 + o1));   // m1 rows 24-31, k hi
            // Gram: b-fragments are the a-fragment registers (row.col, B=A^T)
            mma_tf32(acc[0], a + 0, a[0], a[2]);   // (m0, n0)  cols 0-7
            mma_tf32(acc[1], a + 0, a[1], a[3]);   // (m0, n1)  cols 8-15
            mma_tf32(acc[2], a + 0, a[4], a[6]);   // (m0, n2)  cols 16-23
            mma_tf32(acc[3], a + 0, a[5], a[7]);   // (m0, n3)  cols 24-31
            mma_tf32(acc[4], a + 4, a[4], a[6]);   // (m1, n2)
            mma_tf32(acc[5], a + 4, a[5], a[7]);   // (m1, n3)
        }
    }

    // ── epilogue: scatter the strict upper triangle ──
    // tile coords: i = ioff + lane/4 + 8*(e>>1), j = joff + 2*(lane%4) + (e&1)
    static const int IOFF[6] = { 0, 0, 0, 0, 16, 16 };
    static const int JOFF[6] = { 0, 8, 16, 24, 16, 24 };
    float* ob = out + (batch0 + wid) * NPAIRS;
    const int ib = lane >> 2, jb = 2 * (lane & 3);
    #pragma unroll
    for (int t = 0; t < 6; t++) {
        #pragma unroll
        for (int e = 0; e < 4; e++) {
            const int i = IOFF[t] + ib + 8 * (e >> 1);
            const int j = JOFF[t] + jb + (e & 1);
            if (j > i)
                ob[i * 31 - (i * (i - 1)) / 2 + (j - i - 1)] = acc[t][e];
        }
    }
}

extern "C" void kernel_launch(void* const* d_in, const int* in_sizes, int n_in,
                              void* d_out, int out_size) {
    const float* x = (const float*)d_in[0];
    float* out = (float*)d_out;
    const int nb = in_sizes[0] / (NF * DD);        // 8192
    cudaFuncSetAttribute(soi_mma_kernel,
                         cudaFuncAttributeMaxDynamicSharedMemorySize,
                         NSTAGES * STAGE_BYTES);
    soi_mma_kernel<<<nb / BPC, BLOCK, NSTAGES * STAGE_BYTES>>>(x, out);
}

// round 4
// speedup vs baseline: 3.0091x; 1.6316x over previous
#include <cuda_runtime.h>
#include <cstdint>

// ─────────────────────────────────────────────────────────────────────────────
// SecondOrderFeatureInteraction via mma.sync.m16n8k8.tf32 batched Gram.
//   out[b, pair(i,j)] = dot(x[b,i,:], x[b,j,:]), i<j.  B=8192, N=32, D=256.
// One warp owns one batch end-to-end: warp-private 3-stage cp.async pipeline
// (no block syncs), coalesced 4-line loads, 32x32 gram in 24 accumulators.
// Gram symmetry: B-fragments == A-fragments, so 8 LDS + 6 MMA per k-step.
// ─────────────────────────────────────────────────────────────────────────────

static constexpr int NF = 32, DD = 256, NPAIRS = 496;
static constexpr int BLOCK = 256;                 // 8 warps
static constexpr int BPC = 8;                     // batches per CTA (1/warp)
static constexpr int KC = 32;                     // k-extent per stage
static constexpr int STAGE_BYTES = BPC * NF * KC * 4;   // 32 KB
static constexpr int NSTAGES = 3;
static constexpr int NKST = DD / KC;              // 8 k-stages

#define DI __device__ __forceinline__

DI uint32_t smem_u32(const void* p) {
    uint32_t a;
    asm("{ .reg .u64 t; cvta.to.shared.u64 t, %1; cvt.u32.u64 %0, t; }"
        : "=r"(a) : "l"(p));
    return a;
}

DI void cp_async16(uint32_t dst, const void* src) {
    asm volatile("cp.async.cg.shared.global [%0], [%1], 16;"
                 :: "r"(dst), "l"(src) : "memory");
}

DI float lds_f32(uint32_t a) {
    float v;
    asm volatile("ld.shared.f32 %0, [%1];" : "=f"(v) : "r"(a));
    return v;
}

DI uint32_t to_tf32(float f) {
    uint32_t r;
    asm("cvt.rna.tf32.f32 %0, %1;" : "=r"(r) : "f"(f));
    return r;
}

DI void mma_tf32(float* d, const uint32_t* a, uint32_t b0, uint32_t b1) {
    asm volatile(
        "mma.sync.aligned.m16n8k8.row.col.f32.tf32.tf32.f32 "
        "{%0,%1,%2,%3}, {%4,%5,%6,%7}, {%8,%9}, {%0,%1,%2,%3};"
        : "+f"(d[0]), "+f"(d[1]), "+f"(d[2]), "+f"(d[3])
        : "r"(a[0]), "r"(a[1]), "r"(a[2]), "r"(a[3]), "r"(b0), "r"(b1));
}

extern __shared__ char dynsmem[];

__global__ void __launch_bounds__(BLOCK, 2)
soi_mma_kernel(const float* __restrict__ x, float* __restrict__ out) {
    const uint32_t sb = smem_u32(dynsmem);
    const int tid = threadIdx.x, lane = tid & 31, wid = tid >> 5;
    const long long batch0 = (long long)blockIdx.x * BPC;
    // warp w's global base: its own batch's 32 rows
    const float* xg = x + (batch0 + wid) * (NF * DD);

    // ── warp-private stage loader: 32 rows x 32 floats (4 KB), coalesced.
    //    lane -> (rr = lane>>3 row-in-quad, cc = lane&7 16B chunk);
    //    instr i covers rows 4i..4i+3: 4 contiguous 128B lines per instr.
    const int rr = lane >> 3, cc = lane & 7;
    auto load_stage = [&](int ks) {
        const uint32_t buf = sb + (ks % NSTAGES) * STAGE_BYTES;
        #pragma unroll
        for (int i = 0; i < 8; i++) {
            const int row = 4 * i + rr;                       // row within batch
            const float* src = xg + (long long)row * DD + ks * KC + cc * 4;
            const uint32_t dst = buf + (uint32_t)(wid * NF + row) * 128
                               + (uint32_t)((cc ^ (row & 7)) << 4);
            cp_async16(dst, src);
        }
        asm volatile("cp.async.commit_group;" ::: "memory");
    };

    // ── fragment addressing (consumer layout identical to loader's dst) ──
    const int r7 = lane >> 2;                     // row-in-8, also swizzle key
    const uint32_t rowA = (uint32_t)(wid * NF + r7) * 128 + (lane & 3) * 4;

    float acc[6][4];
    #pragma unroll
    for (int t = 0; t < 6; t++)
        #pragma unroll
        for (int e = 0; e < 4; e++) acc[t][e] = 0.f;

    load_stage(0);
    load_stage(1);

    for (int ks = 0; ks < NKST; ks++) {
        if (ks < NKST - 1)
            asm volatile("cp.async.wait_group 1;" ::: "memory");
        else
            asm volatile("cp.async.wait_group 0;" ::: "memory");
        __syncwarp();                              // warp-private buffers only
        if (ks + 2 < NKST) load_stage(ks + 2);     // refill retired buffer

        const uint32_t buf = sb + (ks % NSTAGES) * STAGE_BYTES;
        #pragma unroll
        for (int kq = 0; kq < 4; kq++) {
            const uint32_t o0 = (uint32_t)(((2 * kq + 0) ^ r7) << 4);
            const uint32_t o1 = (uint32_t)(((2 * kq + 1) ^ r7) << 4);
            const uint32_t base = buf + rowA;
            uint32_t a[8];
            a[0] = to_tf32(lds_f32(base + o0));          // rows 0-7,  k lo
            a[1] = to_tf32(lds_f32(base + 1024 + o0));   // rows 8-15, k lo
            a[2] = to_tf32(lds_f32(base + o1));          // rows 0-7,  k hi
            a[3] = to_tf32(lds_f32(base + 1024 + o1));   // rows 8-15, k hi
            a[4] = to_tf32(lds_f32(base + 2048 + o0));   // rows 16-23, k lo
            a[5] = to_tf32(lds_f32(base + 3072 + o0));   // rows 24-31, k lo
            a[6] = to_tf32(lds_f32(base + 2048 + o1));   // rows 16-23, k hi
            a[7] = to_tf32(lds_f32(base + 3072 + o1));   // rows 24-31, k hi
            // Gram: b-fragments are the a-fragment registers (row.col, B=A^T)
            mma_tf32(acc[0], a + 0, a[0], a[2]);   // (m0, n0)
            mma_tf32(acc[1], a + 0, a[1], a[3]);   // (m0, n1)
            mma_tf32(acc[2], a + 0, a[4], a[6]);   // (m0, n2)
            mma_tf32(acc[3], a + 0, a[5], a[7]);   // (m0, n3)
            mma_tf32(acc[4], a + 4, a[4], a[6]);   // (m1, n2)
            mma_tf32(acc[5], a + 4, a[5], a[7]);   // (m1, n3)
        }
        __syncwarp();                              // reads done before refill next iter
    }

    // ── epilogue: scatter the strict upper triangle ──
    static const int IOFF[6] = { 0, 0, 0, 0, 16, 16 };
    static const int JOFF[6] = { 0, 8, 16, 24, 16, 24 };
    float* ob = out + (batch0 + wid) * NPAIRS;
    const int ib = lane >> 2, jb = 2 * (lane & 3);
    #pragma unroll
    for (int t = 0; t < 6; t++) {
        #pragma unroll
        for (int e = 0; e < 4; e++) {
            const int i = IOFF[t] + ib + 8 * (e >> 1);
            const int j = JOFF[t] + jb + (e & 1);
            if (j > i)
                ob[i * 31 - (i * (i - 1)) / 2 + (j - i - 1)] = acc[t][e];
        }
    }
}

extern "C" void kernel_launch(void* const* d_in, const int* in_sizes, int n_in,
                              void* d_out, int out_size) {
    const float* x = (const float*)d_in[0];
    float* out = (float*)d_out;
    const int nb = in_sizes[0] / (NF * DD);        // 8192
    cudaFuncSetAttribute(soi_mma_kernel,
                         cudaFuncAttributeMaxDynamicSharedMemorySize,
                         NSTAGES * STAGE_BYTES);
    soi_mma_kernel<<<nb / BPC, BLOCK, NSTAGES * STAGE_BYTES>>>(x, out);
}